// round 16
// baseline (speedup 1.0000x reference)
#include <cuda_runtime.h>
#include <math_constants.h>

#define BB 512
#define NN 90
#define DD 1024
#define KK 45
#define THREADS 256
#define WPC 8                      // warps per CTA
#define SCORE_ITEMS 30             // 3 nodes each (both tensors)
#define SEL_SLOT 30
#define GATHER_ITEMS 15            // 6 output rows each
#define SLOTS_PER_Q 46
#define LSEL 80                    // selection lags scores (batches)
#define LGATH 90                   // gathers lag scores (batches)
#define TOT_Q (BB + LGATH)
#define TOTAL_SLOTS (SLOTS_PER_Q * TOT_Q)

// Device-global scratch (no allocation allowed)
__device__ unsigned g_done;
__device__ unsigned g_arrive[BB];
__device__ unsigned g_ready[BB];
__device__ float    g_scores[BB][NN];
__device__ int      g_sel_idx[BB][KK];
__device__ float    g_sel_w[BB][KK];

__global__ __launch_bounds__(THREADS, 4)
void multig_pool_kernel(const float* __restrict__ x_sc,
                        const float* __restrict__ x_fc,
                        const float* __restrict__ pool_w,
                        const float* __restrict__ multi_w,
                        const float* __restrict__ multi_b,
                        float* __restrict__ out)
{
    __shared__ __align__(16) float spw[DD];
    __shared__ float red[WPC];
    __shared__ float s_invnorm;

    const int tid  = threadIdx.x;
    const int wid  = tid >> 5;
    const int lane = tid & 31;

    // ---- Once per CTA: stage pool_w, compute 1/||pool_w|| ----
    float pw2 = 0.f;
    #pragma unroll
    for (int i = 0; i < 4; i++) {
        float v = pool_w[tid + i * THREADS];
        spw[tid + i * THREADS] = v;
        pw2 += v * v;
    }
    #pragma unroll
    for (int off = 16; off; off >>= 1) pw2 += __shfl_xor_sync(0xffffffffu, pw2, off);
    if (lane == 0) red[wid] = pw2;
    __syncthreads();
    if (tid == 0) {
        float s = 0.f;
        #pragma unroll
        for (int i = 0; i < WPC; i++) s += red[i];
        s_invnorm = rsqrtf(s);
    }
    __syncthreads();

    const float inv_norm = s_invnorm;
    const float mw0 = multi_w[0];
    const float mw1 = multi_w[1];
    const float4* __restrict__ pw4 = (const float4*)spw;

    // ---- Warp-autonomous static schedule: NO __syncthreads in this loop.
    // Global slot u -> (Q = u/46, s = u%46):
    //   s < 30 : score nodes 3s..3s+2 of batch Q (both tensors)
    //   s == 30: top-45 selection of batch Q-LSEL (one warp, shfl-ranked)
    //   s > 30 : gather rows 6(s-31)..+5 of batch Q-LGATH
    // Dependencies guarded by per-batch arrive/ready counters; spins are
    // warp-level (cheap) and bounded by the lag structure.
    const unsigned W = gridDim.x * WPC;
    const unsigned u0 = blockIdx.x * WPC + (unsigned)wid;

    for (unsigned u = u0; u < TOTAL_SLOTS; u += W) {
        const unsigned Q = u / SLOTS_PER_Q;
        const unsigned s = u % SLOTS_PER_Q;

        if (s < SCORE_ITEMS) {
            // ========== SCORE ITEM: batch Q, nodes 3s..3s+2 ==========
            if (Q < BB) {
                const int b = (int)Q;
                const float* __restrict__ xb_sc = x_sc + (size_t)b * NN * DD;
                const float* __restrict__ xb_fc = x_fc + (size_t)b * NN * DD;
                #pragma unroll
                for (int d3 = 0; d3 < 3; d3++) {
                    const int n = 3 * (int)s + d3;
                    const float4* rs = (const float4*)(xb_sc + (size_t)n * DD);
                    const float4* rf = (const float4*)(xb_fc + (size_t)n * DD);
                    float dsc = 0.f, dfc = 0.f;
                    #pragma unroll
                    for (int i = 0; i < 8; i++) {
                        int j = lane + i * 32;
                        float4 a = rs[j];
                        float4 c = rf[j];
                        float4 p = pw4[j];
                        dsc += a.x * p.x + a.y * p.y + a.z * p.z + a.w * p.w;
                        dfc += c.x * p.x + c.y * p.y + c.z * p.z + c.w * p.w;
                    }
                    #pragma unroll
                    for (int off = 16; off; off >>= 1) {
                        dsc += __shfl_xor_sync(0xffffffffu, dsc, off);
                        dfc += __shfl_xor_sync(0xffffffffu, dfc, off);
                    }
                    if (lane == 0) {
                        float t0 = tanhf(dsc * inv_norm);
                        float t1 = tanhf(dfc * inv_norm);
                        float z  = t0 * mw0 + t1 * mw1 + multi_b[n];
                        g_scores[b][n] = 1.f / (1.f + expf(-z));
                    }
                }
                if (lane == 0) {
                    __threadfence();
                    atomicAdd(&g_arrive[b], 1u);
                }
            }
        } else if (s == SEL_SLOT) {
            // ========== SELECTION: batch Q-LSEL (single warp) ==========
            if (Q >= LSEL && Q - LSEL < BB) {
                const int b = (int)(Q - LSEL);
                if (lane == 0) {
                    while (atomicAdd(&g_arrive[b], 0u) < SCORE_ITEMS) { }
                }
                __syncwarp();
                __threadfence();

                // Lane l holds scores for nodes l, l+32, l+64 (invalid -> -inf)
                float my0 = __ldcg(&g_scores[b][lane]);
                float my1 = __ldcg(&g_scores[b][lane + 32]);
                float my2 = (lane + 64 < NN) ? __ldcg(&g_scores[b][lane + 64])
                                             : -CUDART_INF_F;
                int r0 = 0, r1 = 0, r2 = 0;
                #pragma unroll 10
                for (int j = 0; j < NN; j++) {
                    float own = (j < 32) ? my0 : ((j < 64) ? my1 : my2);
                    float sj = __shfl_sync(0xffffffffu, own, j & 31);
                    r0 += (sj > my0) || (sj == my0 && j < lane);
                    r1 += (sj > my1) || (sj == my1 && j < lane + 32);
                    r2 += (sj > my2) || (sj == my2 && j < lane + 64);
                }
                if (r0 < KK) { g_sel_idx[b][r0] = lane;      g_sel_w[b][r0] = my0; }
                if (r1 < KK) { g_sel_idx[b][r1] = lane + 32; g_sel_w[b][r1] = my1; }
                if (lane + 64 < NN && r2 < KK) {
                    g_sel_idx[b][r2] = lane + 64; g_sel_w[b][r2] = my2;
                }
                __threadfence();
                if (lane == 0) atomicExch(&g_ready[b], 1u);
            }
        } else {
            // ========== GATHER ITEM: batch Q-LGATH, rows 6g..6g+5 ==========
            if (Q >= LGATH && Q - LGATH < BB) {
                const int b = (int)(Q - LGATH);
                const int g = (int)(s - SEL_SLOT - 1);   // 0..14
                if (lane == 0) {
                    while (atomicAdd(&g_ready[b], 0u) == 0u) { }
                }
                __syncwarp();
                __threadfence();

                const float* __restrict__ xb_sc = x_sc + (size_t)b * NN * DD;
                const float* __restrict__ xb_fc = x_fc + (size_t)b * NN * DD;
                float* __restrict__ out_sc = out + (size_t)b * KK * DD;
                float* __restrict__ out_fc = out + (size_t)BB * KK * DD
                                                 + (size_t)b * KK * DD;

                #pragma unroll
                for (int pp = 0; pp < 3; pp++) {
                    const int rrA = 6 * g + 2 * pp;
                    const int rrB = rrA + 1;
                    const bool scA = (rrA < KK), scB = (rrB < KK);
                    const int  kA = scA ? rrA : rrA - KK;
                    const int  kB = scB ? rrB : rrB - KK;
                    const int  nA = __ldcg(&g_sel_idx[b][kA]);
                    const int  nB = __ldcg(&g_sel_idx[b][kB]);
                    const float wA = __ldcg(&g_sel_w[b][kA]);
                    const float wB = __ldcg(&g_sel_w[b][kB]);
                    const float4* sA = (const float4*)
                        ((scA ? xb_sc : xb_fc) + (size_t)nA * DD);
                    const float4* sB = (const float4*)
                        ((scB ? xb_sc : xb_fc) + (size_t)nB * DD);
                    float4* dA = (float4*)((scA ? out_sc : out_fc) + (size_t)kA * DD);
                    float4* dB = (float4*)((scB ? out_sc : out_fc) + (size_t)kB * DD);
                    #pragma unroll
                    for (int i = 0; i < 8; i++) {
                        int j = lane + i * 32;
                        float4 vA = sA[j];
                        float4 vB = sB[j];
                        vA.x *= wA; vA.y *= wA; vA.z *= wA; vA.w *= wA;
                        vB.x *= wB; vB.y *= wB; vB.z *= wB; vB.w *= wB;
                        dA[j] = vA;
                        dB[j] = vB;
                    }
                }
            }
        }
    }

    // ---- Last CTA out resets device state for the next graph replay ----
    __shared__ unsigned s_is_last;
    __syncthreads();
    if (tid == 0) {
        unsigned d = atomicAdd(&g_done, 1u) + 1u;
        s_is_last = (d == gridDim.x) ? 1u : 0u;
    }
    __syncthreads();
    if (s_is_last) {
        for (int i = tid; i < BB; i += THREADS) {
            g_arrive[i] = 0;
            g_ready[i]  = 0;
        }
        __syncthreads();
        if (tid == 0) {
            __threadfence();
            g_done = 0;
        }
    }
}

extern "C" void kernel_launch(void* const* d_in, const int* in_sizes, int n_in,
                              void* d_out, int out_size)
{
    const float* x_sc    = (const float*)d_in[0];
    const float* x_fc    = (const float*)d_in[1];
    const float* pool_w  = (const float*)d_in[2];
    const float* multi_w = (const float*)d_in[3];
    const float* multi_b = (const float*)d_in[4];
    float* out = (float*)d_out;

    static int grid = 0;
    if (grid == 0) {
        int sm = 0;
        cudaDeviceGetAttribute(&sm, cudaDevAttrMultiProcessorCount, 0);
        if (sm <= 0) sm = 148;
        grid = 4 * sm;   // 4 CTAs/SM x 256 thr, all co-resident
    }

    multig_pool_kernel<<<grid, THREADS>>>(x_sc, x_fc, pool_w, multi_w, multi_b, out);
}

// round 17
// speedup vs baseline: 1.2732x; 1.2732x over previous
#include <cuda_runtime.h>
#include <math_constants.h>

#define BB 512
#define NN 90
#define DD 1024
#define KK 45
#define THREADS 256
#define WPC 8
#define LAG 55                               // gather lags score by LAG batches
#define QTOT (BB + LAG)
#define TOTAL_TASKS (12 * QTOT)
#define ARRIVALS_PER_BATCH 64                // 8 score tasks x 8 warp-arrivals

// Device-global scratch (no allocation allowed)
__device__ unsigned g_done;
__device__ unsigned g_arrive[BB];
__device__ float    g_scores[BB][NN];

__global__ __launch_bounds__(THREADS, 4)
void multig_pool_kernel(const float* __restrict__ x_sc,
                        const float* __restrict__ x_fc,
                        const float* __restrict__ pool_w,
                        const float* __restrict__ multi_w,
                        const float* __restrict__ multi_b,
                        float* __restrict__ out)
{
    __shared__ __align__(16) float spw[DD];
    __shared__ float red[WPC];
    __shared__ float s_invnorm;

    const int tid  = threadIdx.x;
    const int wid  = tid >> 5;
    const int lane = tid & 31;

    // ---- Once per CTA: stage pool_w, compute 1/||pool_w|| ----
    float pw2 = 0.f;
    #pragma unroll
    for (int i = 0; i < 4; i++) {
        float v = pool_w[tid + i * THREADS];
        spw[tid + i * THREADS] = v;
        pw2 += v * v;
    }
    #pragma unroll
    for (int off = 16; off; off >>= 1) pw2 += __shfl_xor_sync(0xffffffffu, pw2, off);
    if (lane == 0) red[wid] = pw2;
    __syncthreads();
    if (tid == 0) {
        float s = 0.f;
        #pragma unroll
        for (int i = 0; i < WPC; i++) s += red[i];
        s_invnorm = rsqrtf(s);
    }
    __syncthreads();

    const float inv_norm = s_invnorm;
    const float mw0 = multi_w[0];
    const float mw1 = multi_w[1];
    const float4* __restrict__ pw4 = (const float4*)spw;

    // ---- Static CTA-aligned schedule, ZERO in-loop __syncthreads.
    // Task t = 12q + r (CTA c takes t = c, c+G, ...):
    //   r < 8 : score eighth r of batch q   (nodes r + 8j; warp w takes
    //           j = w and j = w+8) — each warp arrives independently.
    //   r >= 8: gather quarter (r-8) of batch q-LAG — each warp spins on
    //           g_arrive==64, warp-ranks the 90 scores in registers, copies
    //           its own rows. No barriers anywhere.
    // Dequeue distance 12*LAG = 660 > 592-CTA concurrency + drift margin.
    const unsigned G = gridDim.x;
    for (unsigned t = blockIdx.x; t < TOTAL_TASKS; t += G) {
        const unsigned q = t / 12u;
        const unsigned r = t % 12u;

        if (r < 8u) {
            // ============ SCORE EIGHTH (warp-async) ============
            if (q < BB) {
                const int b = (int)q;
                const int e = (int)r;
                const float* __restrict__ xb_sc = x_sc + (size_t)b * NN * DD;
                const float* __restrict__ xb_fc = x_fc + (size_t)b * NN * DD;

                const int cnt = (NN - e + 7) >> 3;    // 12 (e<2) or 11
                const int na = e + 8 * wid;           // j = wid, always < cnt
                const int nb = e + 8 * (wid + 8);     // j = wid+8, maybe invalid
                const bool hb = (wid + 8) < cnt;      // warp-uniform

                const float4* rsa = (const float4*)(xb_sc + (size_t)na * DD);
                const float4* rfa = (const float4*)(xb_fc + (size_t)na * DD);
                const float4* rsb = (const float4*)(xb_sc + (size_t)(hb ? nb : na) * DD);
                const float4* rfb = (const float4*)(xb_fc + (size_t)(hb ? nb : na) * DD);

                float dsa = 0.f, dfa = 0.f, dsb = 0.f, dfb = 0.f;
                #pragma unroll
                for (int i = 0; i < 8; i++) {
                    int j = lane + i * 32;
                    float4 p = pw4[j];
                    float4 a0 = rsa[j];
                    float4 a1 = rfa[j];
                    dsa += a0.x * p.x + a0.y * p.y + a0.z * p.z + a0.w * p.w;
                    dfa += a1.x * p.x + a1.y * p.y + a1.z * p.z + a1.w * p.w;
                    if (hb) {
                        float4 b0 = rsb[j];
                        float4 b1 = rfb[j];
                        dsb += b0.x * p.x + b0.y * p.y + b0.z * p.z + b0.w * p.w;
                        dfb += b1.x * p.x + b1.y * p.y + b1.z * p.z + b1.w * p.w;
                    }
                }
                #pragma unroll
                for (int off = 16; off; off >>= 1) {
                    dsa += __shfl_xor_sync(0xffffffffu, dsa, off);
                    dfa += __shfl_xor_sync(0xffffffffu, dfa, off);
                    dsb += __shfl_xor_sync(0xffffffffu, dsb, off);
                    dfb += __shfl_xor_sync(0xffffffffu, dfb, off);
                }
                if (lane == 0) {
                    float t0 = tanhf(dsa * inv_norm);
                    float t1 = tanhf(dfa * inv_norm);
                    g_scores[b][na] = 1.f / (1.f + expf(-(t0 * mw0 + t1 * mw1 + multi_b[na])));
                    if (hb) {
                        float t2 = tanhf(dsb * inv_norm);
                        float t3 = tanhf(dfb * inv_norm);
                        g_scores[b][nb] = 1.f / (1.f + expf(-(t2 * mw0 + t3 * mw1 + multi_b[nb])));
                    }
                    __threadfence();
                    atomicAdd(&g_arrive[b], 1u);   // warp-level arrival
                }
            }
        } else {
            // ============ GATHER QUARTER (warp-async) ============
            if (q >= LAG && q - LAG < BB) {
                const int b  = (int)(q - LAG);
                const int qt = (int)(r - 8u);

                if (lane == 0) {
                    while (atomicAdd(&g_arrive[b], 0u) < ARRIVALS_PER_BATCH) { }
                }
                __syncwarp();
                __threadfence();

                // Warp-local top-45 ranking (registers + shfl, no smem)
                float my0 = __ldcg(&g_scores[b][lane]);
                float my1 = __ldcg(&g_scores[b][lane + 32]);
                float my2 = (lane + 64 < NN) ? __ldcg(&g_scores[b][lane + 64])
                                             : -CUDART_INF_F;
                int r0 = 0, r1 = 0, r2 = 0;
                #pragma unroll 10
                for (int j = 0; j < NN; j++) {
                    float own = (j < 32) ? my0 : ((j < 64) ? my1 : my2);
                    float sj = __shfl_sync(0xffffffffu, own, j & 31);
                    r0 += (sj > my0) || (sj == my0 && j < lane);
                    r1 += (sj > my1) || (sj == my1 && j < lane + 32);
                    r2 += (sj > my2) || (sj == my2 && j < lane + 64);
                }
                // Scatter (idx, w) by rank into registers via ballot+shfl:
                // build sel via shared-nothing: each lane may own up to 3
                // ranked entries; broadcast through a small loop over ranks
                // is expensive — instead each lane publishes (rank -> idx,w)
                // pairs via shfl match. Simpler: each warp needs only the
                // rows it copies: rows rr = qt + 4m (m = wid + 8*i).
                // For each such output row k (rank k), find which lane holds
                // rank k via ballot.
                // Pack: lane's candidate ranks are r0, r1, r2.
                const float* __restrict__ xb_sc = x_sc + (size_t)b * NN * DD;
                const float* __restrict__ xb_fc = x_fc + (size_t)b * NN * DD;
                float* __restrict__ out_sc = out + (size_t)b * KK * DD;
                float* __restrict__ out_fc = out + (size_t)BB * KK * DD
                                                 + (size_t)b * KK * DD;

                // This warp copies output rows rr = qt + 4m for
                // m = wid, wid+8, wid+16 (those < cnt2), where cnt2 covers
                // 2*KK = 90 rows. Warp handles up to 3 rows.
                const int cnt2 = (2 * KK - qt + 3) >> 2;   // 23 or 22
                for (int m = wid; m < cnt2; m += WPC) {
                    const int rr = qt + 4 * m;
                    const bool is_sc = (rr < KK);
                    const int  k = is_sc ? rr : rr - KK;   // target rank
                    // find lane+slot holding rank k
                    unsigned m0 = __ballot_sync(0xffffffffu, r0 == k);
                    unsigned m1 = __ballot_sync(0xffffffffu, r1 == k);
                    unsigned m2 = __ballot_sync(0xffffffffu, r2 == k);
                    int src_lane; float myv; int myn;
                    if (m0) { src_lane = __ffs(m0) - 1; myv = my0; myn = src_lane; }
                    else if (m1) { src_lane = __ffs(m1) - 1; myv = my1; myn = src_lane + 32; }
                    else { src_lane = __ffs(m2) - 1; myv = my2; myn = src_lane + 64; }
                    const float w = __shfl_sync(0xffffffffu, myv, src_lane);
                    const int   n = __shfl_sync(0xffffffffu, myn, src_lane);

                    const float4* src = (const float4*)
                        ((is_sc ? xb_sc : xb_fc) + (size_t)n * DD);
                    float4* dst = (float4*)
                        ((is_sc ? out_sc : out_fc) + (size_t)k * DD);
                    #pragma unroll
                    for (int i = 0; i < 8; i++) {
                        int j = lane + i * 32;
                        float4 v = src[j];
                        v.x *= w; v.y *= w; v.z *= w; v.w *= w;
                        dst[j] = v;
                    }
                }
            }
        }
    }

    // ---- Last CTA out resets device state for the next graph replay ----
    __shared__ unsigned s_is_last;
    __syncthreads();
    if (tid == 0) {
        unsigned d = atomicAdd(&g_done, 1u) + 1u;
        s_is_last = (d == gridDim.x) ? 1u : 0u;
    }
    __syncthreads();
    if (s_is_last) {
        for (int i = tid; i < BB; i += THREADS) g_arrive[i] = 0;
        __syncthreads();
        if (tid == 0) {
            __threadfence();
            g_done = 0;
        }
    }
}

extern "C" void kernel_launch(void* const* d_in, const int* in_sizes, int n_in,
                              void* d_out, int out_size)
{
    const float* x_sc    = (const float*)d_in[0];
    const float* x_fc    = (const float*)d_in[1];
    const float* pool_w  = (const float*)d_in[2];
    const float* multi_w = (const float*)d_in[3];
    const float* multi_b = (const float*)d_in[4];
    float* out = (float*)d_out;

    static int grid = 0;
    if (grid == 0) {
        int sm = 0;
        cudaDeviceGetAttribute(&sm, cudaDevAttrMultiProcessorCount, 0);
        if (sm <= 0) sm = 148;
        grid = 4 * sm;   // 4 CTAs/SM x 256 thr
    }

    multig_pool_kernel<<<grid, THREADS>>>(x_sc, x_fc, pool_w, multi_w, multi_b, out);
}